// round 6
// baseline (speedup 1.0000x reference)
#include <cuda_runtime.h>
#include <cuda_bf16.h>
#include <math.h>

// Problem constants
#define TT     1024
#define DD     4
#define PP     8
#define DPW    32                    // D*P
#define SS     256                   // N * N_SAMPLE
#define LT     8                     // timesteps per chunk
#define NCHUNK 128                   // chunks along T (128*8 = 1024)
#define TBL    (TT*DPW)              // 32768 table elements
#define SZ     ((size_t)SS*TT*DPW)   // 8388608 elements per output tensor
#define HLOG2PI 0.91893853320467274178f

// Precomputed per-(t,dp) tables (allocation-free scratch)
__device__ float g_mean[TBL];
__device__ float g_sw[TBL];
__device__ float g_amul[TT*DD];      // sigmoid(a_raw[t-1,d]), amul[0,*]=0

// ---------------------------------------------------------------------------
// K0: precompute per-(t,dp) tables (c0 table dropped; lp uses __logf inline).
// ---------------------------------------------------------------------------
__global__ void arma_precompute(const float* __restrict__ m,
                                const float* __restrict__ s_raw,
                                const float* __restrict__ a_raw,
                                const int*   __restrict__ dim_idx)
{
    int idx = blockIdx.x * blockDim.x + threadIdx.x;
    if (idx >= TBL) return;
    int t  = idx >> 5;
    int dp = idx & 31;
    int dd = dp >> 3;
    int p  = dp & 7;
    int src = dim_idx[dd];

    float am = 0.0f;
    if (t > 0) {
        float x = a_raw[(t - 1) * DD + src];
        am = 1.0f / (1.0f + __expf(-x));
    }

    float sv = s_raw[t * DPW + src * PP + p];
    float sw = (sv > 20.0f) ? sv : __logf(1.0f + __expf(sv));   // softplus
    float mn = (1.0f - am) * m[t * DPW + src * PP + p];

    g_mean[idx] = mn;
    g_sw[idx]   = sw;
    if (p == 0) g_amul[t * DD + dd] = am;
}

// ---------------------------------------------------------------------------
// Fused main kernel: one block per sample s; 1024 threads = 128 chunks x 8 quads.
//  Phase A: stream noise once (__ldcs), write lp (__stcs, computed via __logf),
//           keep z[8] (float4) in registers, build chunk summary b.
//  Phase B: per-chunk amul products (in-block).
//  Phase C: 32 threads run the 128-step carry chain in smem.
//  Phase D: replay recursion from registers, final param store (__stcs).
// No param round trip, no c0 table. DRAM traffic = 32MB in + 64MB out.
// ---------------------------------------------------------------------------
__global__ void __launch_bounds__(1024, 1)
arma_fused(const float4* __restrict__ noise4,
           float4* __restrict__ param4,
           float4* __restrict__ lp4,
           int write_lp)
{
    const int s     = blockIdx.x;
    const int tid   = threadIdx.x;
    const int q     = tid & 7;            // dp quad: dp = 4q..4q+3
    const int chunk = tid >> 3;           // 0..127
    const int dd    = q >> 1;             // output dim, uniform in quad
    const int t0    = chunk << 3;

    __shared__ float s_amul[TT * DD];     // 16 KB
    __shared__ float sB[NCHUNK][DPW];     // 16 KB  per-chunk local end values
    __shared__ float sA[NCHUNK][DD];      // 2 KB   per-chunk amul products
    __shared__ float sC[NCHUNK][DPW];     // 16 KB  exclusive carries

    for (int i = tid; i < TT * DD; i += 1024) s_amul[i] = g_amul[i];
    __syncthreads();

    const float4* tbl_sw = (const float4*)g_sw;
    const float4* tbl_mn = (const float4*)g_mean;

    const size_t base = ((size_t)((s << 10) + t0) << 3) + q;   // float4 index

    // ---- Phase A: z in regs, lp out, chunk summary b ----
    float4 z[LT];
    float4 b = make_float4(0.f, 0.f, 0.f, 0.f);

#pragma unroll
    for (int i = 0; i < LT; i++) {
        const int t  = t0 + i;
        const int ti = (t << 3) + q;
        const float4 n  = __ldcs(&noise4[base + (size_t)i * 8]);  // read once
        const float4 sw = tbl_sw[ti];
        const float4 mn = tbl_mn[ti];
        if (write_lp) {
            float4 lp;
            lp.x = fmaf(-0.5f * n.x, n.x, -__logf(sw.x) - HLOG2PI);
            lp.y = fmaf(-0.5f * n.y, n.y, -__logf(sw.y) - HLOG2PI);
            lp.z = fmaf(-0.5f * n.z, n.z, -__logf(sw.z) - HLOG2PI);
            lp.w = fmaf(-0.5f * n.w, n.w, -__logf(sw.w) - HLOG2PI);
            __stcs(&lp4[base + (size_t)i * 8], lp);
        }
        float4 zz;
        zz.x = fmaf(sw.x, n.x, mn.x);
        zz.y = fmaf(sw.y, n.y, mn.y);
        zz.z = fmaf(sw.z, n.z, mn.z);
        zz.w = fmaf(sw.w, n.w, mn.w);
        z[i] = zz;
        const float am = s_amul[(t << 2) + dd];
        b.x = fmaf(am, b.x, zz.x);
        b.y = fmaf(am, b.y, zz.y);
        b.z = fmaf(am, b.z, zz.z);
        b.w = fmaf(am, b.w, zz.w);
    }
    ((float4*)sB[chunk])[q] = b;

    // ---- Phase B: per-chunk amul products (512 threads, 8 muls each) ----
    if (tid < NCHUNK * DD) {
        const int c  = tid >> 2;
        const int d2 = tid & 3;
        float a = 1.0f;
        const int tb = c << 3;
#pragma unroll
        for (int i = 0; i < LT; i++)
            a *= s_amul[((tb + i) << 2) + d2];
        sA[c][d2] = a;
    }
    __syncthreads();

    // ---- Phase C: serial affine scan; 32 threads, one per dp chain ----
    if (tid < 32) {
        const int dp = tid;
        const int d2 = dp >> 3;
        float carry = 0.0f;
#pragma unroll
        for (int c = 0; c < NCHUNK; c++) {
            sC[c][dp] = carry;
            carry = fmaf(sA[c][d2], carry, sB[c][dp]);
        }
    }
    __syncthreads();

    // ---- Phase D: replay recursion from registers (no loads) ----
    float4 pv = ((const float4*)sC[chunk])[q];
#pragma unroll
    for (int i = 0; i < LT; i++) {
        const int t = t0 + i;
        const float am = s_amul[(t << 2) + dd];
        pv.x = fmaf(am, pv.x, z[i].x);
        pv.y = fmaf(am, pv.y, z[i].y);
        pv.z = fmaf(am, pv.z, z[i].z);
        pv.w = fmaf(am, pv.w, z[i].w);
        __stcs(&param4[base + (size_t)i * 8], pv);
    }
}

// ---------------------------------------------------------------------------
// Launch.  Inputs: 0:y 1:age 2:m 3:s_raw 4:a_raw 5:noise 6:cond_sample
//                  7:dim_idx 8:compute_log_prob
// Output: param (S,T,D,P) then log_prob (S,T,D,P), float32.
// ---------------------------------------------------------------------------
extern "C" void kernel_launch(void* const* d_in, const int* in_sizes, int n_in,
                              void* d_out, int out_size)
{
    const float* m      = (const float*)d_in[2];
    const float* s_raw  = (const float*)d_in[3];
    const float* a_raw  = (const float*)d_in[4];
    const float* noise  = (const float*)d_in[5];
    const int*   dimidx = (const int*)  d_in[7];

    float* out_param = (float*)d_out;
    int write_lp = (out_size >= (int)(2 * SZ)) ? 1 : 0;
    float* out_lp = out_param + SZ;

    const float4* noise4 = (const float4*)noise;
    float4* param4 = (float4*)out_param;
    float4* lp4    = (float4*)(write_lp ? out_lp : out_param);

    arma_precompute<<<128, 256>>>(m, s_raw, a_raw, dimidx);
    arma_fused<<<SS, 1024>>>(noise4, param4, lp4, write_lp);
}